// round 8
// baseline (speedup 1.0000x reference)
#include <cuda_runtime.h>
#include <cuda_bf16.h>

typedef unsigned long long u64;

// ---------------- packed f32x2 helpers ----------------
__device__ __forceinline__ u64 fma2(u64 a, u64 b, u64 c) {
    u64 d;
    asm("fma.rn.f32x2 %0, %1, %2, %3;" : "=l"(d) : "l"(a), "l"(b), "l"(c));
    return d;
}
__device__ __forceinline__ u64 mul2(u64 a, u64 b) {
    u64 d;
    asm("mul.rn.f32x2 %0, %1, %2;" : "=l"(d) : "l"(a), "l"(b));
    return d;
}
__device__ __forceinline__ u64 add2(u64 a, u64 b) {
    u64 d;
    asm("add.rn.f32x2 %0, %1, %2;" : "=l"(d) : "l"(a), "l"(b));
    return d;
}
__device__ __forceinline__ u64 pack2(float x, float y) {
    u64 r;
    asm("mov.b64 %0, {%1, %2};" : "=l"(r) : "f"(x), "f"(y));
    return r;
}
__device__ __forceinline__ void unpack2(u64 v, float& x, float& y) {
    asm("mov.b64 {%0, %1}, %2;" : "=f"(x), "=f"(y) : "l"(v));
}
__device__ __forceinline__ u64 dup2(float f) {
    unsigned u = __float_as_uint(f);
    return ((u64)u << 32) | (u64)u;
}

#define R_CONST 3.82843f

// ---------------- packed activation ----------------
// act(x) = logistic^2( cos(x)*0.5 + 0.5 ),  logistic(u) = R*u*(1-u)
// FOLD_R==0: the final multiply by R is folded into the NEXT layer's weights.
template <int FOLD_R>
__device__ __forceinline__ u64 act2_t(u64 v) {
    const u64 INVPI  = dup2(0.31830988618379067f);
    const u64 MAGIC  = dup2(12582912.0f);          // 1.5 * 2^23
    const u64 NMAGIC = dup2(-12582912.0f);
    const u64 NPIHI  = dup2(-3.14159274101257324f);
    const u64 PMID   = dup2(8.742277657347586e-8f);
    const u64 ONE    = dup2(1.0f);
    const u64 NONE   = dup2(-1.0f);
    const u64 HALF   = dup2(0.5f);
    const u64 NHALF  = dup2(-0.5f);
    const u64 C8     = dup2(2.443315711809948e-5f);
    const u64 C6     = dup2(-1.388731625493765e-3f);
    const u64 C4     = dup2(4.166664568298827e-2f);
    const u64 RR     = dup2(R_CONST);

    u64 m = fma2(v, INVPI, MAGIC);
    u64 q = add2(m, NMAGIC);
    u64 r = fma2(q, NPIHI, v);
    r = fma2(q, PMID, r);            // r = v - q*pi, |r| <= pi/2

    u64 s = mul2(r, r);
    u64 p = fma2(s, C8, C6);
    p = fma2(s, p, C4);
    u64 t = fma2(s, NHALF, ONE);
    u64 s2 = mul2(s, s);
    u64 c = fma2(s2, p, t);          // cos(r)

    u64 par = (m << 31) & 0x8000000080000000ULL;  // parity sign of q
    c ^= par;

    u64 u = fma2(c, HALF, HALF);     // into [0,1]
    u64 om = fma2(u, NONE, ONE);
    u = mul2(mul2(u, om), RR);
    om = fma2(u, NONE, ONE);
    u = mul2(u, om);
    if (FOLD_R) u = mul2(u, RR);
    return u;
}

// ---------------- geometry ----------------
#define TPB 128
#define PPB 512            // 4 points per thread

// shared layout (u64 units)
// hs: float4[96 rows][TPB]   rows = 3 banks of 32 (A=0, B=32, C=64)
#define HS_OFF    0                       // 96*128*2 = 24576 u64
#define WP2_OFF   24576                   // u64[64][32] j-pairs, R-scaled
#define WP3_OFF   26624
#define W1X0_OFF  28672                   // 32
#define W1X1_OFF  28704                   // 32
#define W4D_OFF   28736                   // 64 (dup'd, R-scaled)
#define B1P_OFF   28800                   // 32
#define B2P_OFF   28832                   // 32
#define B3P_OFF   28864                   // 32
#define B4D_OFF   28896                   // 1
#define SMEM_U64  28897
#define SMEM_BYTES (SMEM_U64 * 8)         // 231176 B (< 232448 limit)

// One 64->64 layer, 4 points/thread, output-pair lanes.
// IN0: rows for k=0..31, IN1: rows for k=32..63
// O0: rows for outputs 0..31 (tile 0), O1: rows for outputs 32..63 (tile 1)
// O0 = free bank; O1 = IN0's bank (safe: written after all k reads).
template <int IN0, int IN1, int O0, int O1>
__device__ __forceinline__ void layerQ(const u64* __restrict__ wp,
                                       const u64* __restrict__ bp,
                                       float4* __restrict__ hsF, int tid) {
#pragma unroll
    for (int t = 0; t < 2; ++t) {
        const int outRow = (t == 0) ? O0 : O1;
        u64 a0[16], a1[16], a2[16], a3[16];
#pragma unroll
        for (int p = 0; p < 16; ++p) {
            u64 b = bp[t * 16 + p];
            a0[p] = b; a1[p] = b; a2[p] = b; a3[p] = b;
        }
        const u64* wt = wp + t * 16;

#pragma unroll 4
        for (int k = 0; k < 32; ++k) {
            float4 h = hsF[(IN0 + k) * TPB + tid];
            u64 dA = pack2(h.x, h.x), dB = pack2(h.y, h.y);
            u64 dC = pack2(h.z, h.z), dD = pack2(h.w, h.w);
            const ulonglong2* wr = (const ulonglong2*)(wt + k * 32);
#pragma unroll
            for (int p2 = 0; p2 < 8; ++p2) {
                ulonglong2 w = wr[p2];
                a0[2 * p2]     = fma2(dA, w.x, a0[2 * p2]);
                a1[2 * p2]     = fma2(dB, w.x, a1[2 * p2]);
                a2[2 * p2]     = fma2(dC, w.x, a2[2 * p2]);
                a3[2 * p2]     = fma2(dD, w.x, a3[2 * p2]);
                a0[2 * p2 + 1] = fma2(dA, w.y, a0[2 * p2 + 1]);
                a1[2 * p2 + 1] = fma2(dB, w.y, a1[2 * p2 + 1]);
                a2[2 * p2 + 1] = fma2(dC, w.y, a2[2 * p2 + 1]);
                a3[2 * p2 + 1] = fma2(dD, w.y, a3[2 * p2 + 1]);
            }
        }
#pragma unroll 4
        for (int k = 0; k < 32; ++k) {
            float4 h = hsF[(IN1 + k) * TPB + tid];
            u64 dA = pack2(h.x, h.x), dB = pack2(h.y, h.y);
            u64 dC = pack2(h.z, h.z), dD = pack2(h.w, h.w);
            const ulonglong2* wr = (const ulonglong2*)(wt + (32 + k) * 32);
#pragma unroll
            for (int p2 = 0; p2 < 8; ++p2) {
                ulonglong2 w = wr[p2];
                a0[2 * p2]     = fma2(dA, w.x, a0[2 * p2]);
                a1[2 * p2]     = fma2(dB, w.x, a1[2 * p2]);
                a2[2 * p2]     = fma2(dC, w.x, a2[2 * p2]);
                a3[2 * p2]     = fma2(dD, w.x, a3[2 * p2]);
                a0[2 * p2 + 1] = fma2(dA, w.y, a0[2 * p2 + 1]);
                a1[2 * p2 + 1] = fma2(dB, w.y, a1[2 * p2 + 1]);
                a2[2 * p2 + 1] = fma2(dC, w.y, a2[2 * p2 + 1]);
                a3[2 * p2 + 1] = fma2(dD, w.y, a3[2 * p2 + 1]);
            }
        }

        // activation + store: pair p -> rows outRow+2p (lo lanes), +2p+1 (hi)
#pragma unroll
        for (int p = 0; p < 16; ++p) {
            u64 rA = act2_t<0>(a0[p]);
            u64 rB = act2_t<0>(a1[p]);
            u64 rC = act2_t<0>(a2[p]);
            u64 rD = act2_t<0>(a3[p]);
            float xa, ya, xb, yb, xc, yc, xd, yd;
            unpack2(rA, xa, ya); unpack2(rB, xb, yb);
            unpack2(rC, xc, yc); unpack2(rD, xd, yd);
            hsF[(outRow + 2 * p) * TPB + tid]     = make_float4(xa, xb, xc, xd);
            hsF[(outRow + 2 * p + 1) * TPB + tid] = make_float4(ya, yb, yc, yd);
        }
    }
}

__global__ void __launch_bounds__(TPB, 1)
mlp_kernel(const float* __restrict__ x,
           const float* __restrict__ W1, const float* __restrict__ b1,
           const float* __restrict__ W2, const float* __restrict__ b2,
           const float* __restrict__ W3, const float* __restrict__ b3,
           const float* __restrict__ W4, const float* __restrict__ b4,
           float* __restrict__ out, int N) {
    extern __shared__ u64 sm[];
    const int tid = threadIdx.x;

    // ---- stage weights: j-pair packing, R folded into W2/W3/W4 ----
    for (int idx = tid; idx < 2048; idx += TPB) {
        int k = idx >> 5, jp = idx & 31;
        sm[WP2_OFF + idx] = pack2(R_CONST * W2[(2 * jp) * 64 + k],
                                  R_CONST * W2[(2 * jp + 1) * 64 + k]);
        sm[WP3_OFF + idx] = pack2(R_CONST * W3[(2 * jp) * 64 + k],
                                  R_CONST * W3[(2 * jp + 1) * 64 + k]);
    }
    if (tid < 32) {
        sm[W1X0_OFF + tid] = pack2(W1[(2 * tid) * 2 + 0], W1[(2 * tid + 1) * 2 + 0]);
        sm[W1X1_OFF + tid] = pack2(W1[(2 * tid) * 2 + 1], W1[(2 * tid + 1) * 2 + 1]);
        sm[B1P_OFF + tid] = pack2(b1[2 * tid], b1[2 * tid + 1]);
        sm[B2P_OFF + tid] = pack2(b2[2 * tid], b2[2 * tid + 1]);
        sm[B3P_OFF + tid] = pack2(b3[2 * tid], b3[2 * tid + 1]);
    }
    if (tid < 64) sm[W4D_OFF + tid] = dup2(R_CONST * W4[tid]);
    if (tid == 0) sm[B4D_OFF] = dup2(b4[0]);
    __syncthreads();

    float4* hsF = (float4*)(sm + HS_OFF);

    // 4 points per thread, strided by TPB
    const int base = blockIdx.x * PPB + tid;
    const int iA = base, iB = base + TPB, iC = base + 2 * TPB, iD = base + 3 * TPB;
    const bool vA = iA < N, vB = iB < N, vC = iC < N, vD = iD < N;

    float2 xA = vA ? ((const float2*)x)[iA] : make_float2(0.f, 0.f);
    float2 xB = vB ? ((const float2*)x)[iB] : make_float2(0.f, 0.f);
    float2 xC = vC ? ((const float2*)x)[iC] : make_float2(0.f, 0.f);
    float2 xD = vD ? ((const float2*)x)[iD] : make_float2(0.f, 0.f);

    // ---- layer 1: 2 -> 64, outputs -> banks A (rows 0..31) and B (32..63)
    {
        u64 dA0 = pack2(xA.x, xA.x), dA1 = pack2(xA.y, xA.y);
        u64 dB0 = pack2(xB.x, xB.x), dB1 = pack2(xB.y, xB.y);
        u64 dC0 = pack2(xC.x, xC.x), dC1 = pack2(xC.y, xC.y);
        u64 dD0 = pack2(xD.x, xD.x), dD1 = pack2(xD.y, xD.y);
        const u64* w0 = sm + W1X0_OFF;
        const u64* w1 = sm + W1X1_OFF;
        const u64* bp = sm + B1P_OFF;
#pragma unroll 4
        for (int jp = 0; jp < 32; ++jp) {
            u64 wa = w0[jp], wb = w1[jp], bb = bp[jp];
            u64 pA = fma2(dA0, wa, fma2(dA1, wb, bb));
            u64 pB = fma2(dB0, wa, fma2(dB1, wb, bb));
            u64 pC = fma2(dC0, wa, fma2(dC1, wb, bb));
            u64 pD = fma2(dD0, wa, fma2(dD1, wb, bb));
            u64 rA = act2_t<0>(pA), rB = act2_t<0>(pB);
            u64 rC = act2_t<0>(pC), rD = act2_t<0>(pD);
            float xa, ya, xb, yb, xc, yc, xd, yd;
            unpack2(rA, xa, ya); unpack2(rB, xb, yb);
            unpack2(rC, xc, yc); unpack2(rD, xd, yd);
            hsF[(2 * jp) * TPB + tid]     = make_float4(xa, xb, xc, xd);
            hsF[(2 * jp + 1) * TPB + tid] = make_float4(ya, yb, yc, yd);
        }
    }

    // ---- layer 2: in A(0),B(32); t1 -> C(64), t2 -> A(0)
    layerQ<0, 32, 64, 0>(sm + WP2_OFF, sm + B2P_OFF, hsF, tid);
    // ---- layer 3: in C(64),A(0); t1 -> B(32), t2 -> C(64)
    layerQ<64, 0, 32, 64>(sm + WP3_OFF, sm + B3P_OFF, hsF, tid);

    // ---- layer 4: 64 -> 1; in B(32) for k<32, C(64) for k>=32
    {
        const u64* w4d = sm + W4D_OFF;
        // BUGFIX (round 7): BOTH lane-pair chains need the b4 bias seed.
        u64 sAB0 = sm[B4D_OFF], sAB1 = dup2(0.f);
        u64 sCD0 = sm[B4D_OFF], sCD1 = dup2(0.f);
#pragma unroll 8
        for (int k = 0; k < 32; k += 2) {
            float4 h0 = hsF[(32 + k) * TPB + tid];
            float4 h1 = hsF[(33 + k) * TPB + tid];
            u64 w0 = w4d[k], w1 = w4d[k + 1];
            sAB0 = fma2(pack2(h0.x, h0.y), w0, sAB0);
            sCD0 = fma2(pack2(h0.z, h0.w), w0, sCD0);
            sAB1 = fma2(pack2(h1.x, h1.y), w1, sAB1);
            sCD1 = fma2(pack2(h1.z, h1.w), w1, sCD1);
        }
#pragma unroll 8
        for (int k = 0; k < 32; k += 2) {
            float4 h0 = hsF[(64 + k) * TPB + tid];
            float4 h1 = hsF[(65 + k) * TPB + tid];
            u64 w0 = w4d[32 + k], w1 = w4d[33 + k];
            sAB0 = fma2(pack2(h0.x, h0.y), w0, sAB0);
            sCD0 = fma2(pack2(h0.z, h0.w), w0, sCD0);
            sAB1 = fma2(pack2(h1.x, h1.y), w1, sAB1);
            sCD1 = fma2(pack2(h1.z, h1.w), w1, sCD1);
        }
        u64 oAB = act2_t<1>(add2(sAB0, sAB1));
        u64 oCD = act2_t<1>(add2(sCD0, sCD1));
        float oa, ob, oc, od;
        unpack2(oAB, oa, ob);
        unpack2(oCD, oc, od);
        if (vA) out[iA] = oa;
        if (vB) out[iB] = ob;
        if (vC) out[iC] = oc;
        if (vD) out[iD] = od;
    }
}

extern "C" void kernel_launch(void* const* d_in, const int* in_sizes, int n_in,
                              void* d_out, int out_size) {
    const float* x  = (const float*)d_in[0];
    const float* W1 = (const float*)d_in[1];
    const float* b1 = (const float*)d_in[2];
    const float* W2 = (const float*)d_in[3];
    const float* b2 = (const float*)d_in[4];
    const float* W3 = (const float*)d_in[5];
    const float* b3 = (const float*)d_in[6];
    const float* W4 = (const float*)d_in[7];
    const float* b4 = (const float*)d_in[8];
    float* out = (float*)d_out;

    int N = in_sizes[0] / 2;
    int grid = (N + PPB - 1) / PPB;

    cudaFuncSetAttribute(mlp_kernel, cudaFuncAttributeMaxDynamicSharedMemorySize,
                         SMEM_BYTES);
    mlp_kernel<<<grid, TPB, SMEM_BYTES>>>(x, W1, b1, W2, b2, W3, b3, W4, b4,
                                          out, N);
}

// round 11
// speedup vs baseline: 1.7855x; 1.7855x over previous
#include <cuda_runtime.h>
#include <cuda_bf16.h>

typedef unsigned long long u64;

// ---------------- packed f32x2 helpers ----------------
__device__ __forceinline__ u64 fma2(u64 a, u64 b, u64 c) {
    u64 d;
    asm("fma.rn.f32x2 %0, %1, %2, %3;" : "=l"(d) : "l"(a), "l"(b), "l"(c));
    return d;
}
__device__ __forceinline__ u64 mul2(u64 a, u64 b) {
    u64 d;
    asm("mul.rn.f32x2 %0, %1, %2;" : "=l"(d) : "l"(a), "l"(b));
    return d;
}
__device__ __forceinline__ u64 add2(u64 a, u64 b) {
    u64 d;
    asm("add.rn.f32x2 %0, %1, %2;" : "=l"(d) : "l"(a), "l"(b));
    return d;
}
__device__ __forceinline__ u64 pack2(float x, float y) {
    u64 r;
    asm("mov.b64 %0, {%1, %2};" : "=l"(r) : "f"(x), "f"(y));
    return r;
}
__device__ __forceinline__ void unpack2(u64 v, float& x, float& y) {
    asm("mov.b64 {%0, %1}, %2;" : "=f"(x), "=f"(y) : "l"(v));
}
__device__ __forceinline__ u64 dup2(float f) {
    unsigned u = __float_as_uint(f);
    return ((u64)u << 32) | (u64)u;
}

#define R_CONST 3.82843f

// ---------------- constant-memory weights (W2, W3) ----------------
// Packed layout per layer: ulonglong2[1024]; element (k*16 + t*8 + p2)
// holds j-pairs (4q..4q+3) for k, R-folded. Filled at launch by prep kernel
// + cudaMemcpyToSymbolAsync (D2D, graph-capturable).
__constant__ ulonglong2 CW2[1024];
__constant__ ulonglong2 CW3[1024];
__device__ ulonglong2 g_wscratch[2048];

__global__ void prep_kernel(const float* __restrict__ W2,
                            const float* __restrict__ W3) {
    int t = blockIdx.x * blockDim.x + threadIdx.x;  // 0..2047
    if (t >= 2048) return;
    const float* W = (t & 1024) ? W3 : W2;
    int e = t & 1023;
    int k = e >> 4, q = e & 15;
    ulonglong2 v;
    v.x = pack2(R_CONST * W[(4 * q + 0) * 64 + k],
                R_CONST * W[(4 * q + 1) * 64 + k]);
    v.y = pack2(R_CONST * W[(4 * q + 2) * 64 + k],
                R_CONST * W[(4 * q + 3) * 64 + k]);
    g_wscratch[t] = v;
}

// ---------------- packed activation ----------------
// act(x) = logistic^2( cos(x)*0.5 + 0.5 ),  logistic(u) = R*u*(1-u)
// FOLD_R==0: the final multiply by R is folded into the NEXT layer's weights.
template <int FOLD_R>
__device__ __forceinline__ u64 act2_t(u64 v) {
    const u64 INVPI  = dup2(0.31830988618379067f);
    const u64 MAGIC  = dup2(12582912.0f);          // 1.5 * 2^23
    const u64 NMAGIC = dup2(-12582912.0f);
    const u64 NPIHI  = dup2(-3.14159274101257324f);
    const u64 PMID   = dup2(8.742277657347586e-8f);
    const u64 ONE    = dup2(1.0f);
    const u64 NONE   = dup2(-1.0f);
    const u64 HALF   = dup2(0.5f);
    const u64 NHALF  = dup2(-0.5f);
    const u64 C8     = dup2(2.443315711809948e-5f);
    const u64 C6     = dup2(-1.388731625493765e-3f);
    const u64 C4     = dup2(4.166664568298827e-2f);
    const u64 RR     = dup2(R_CONST);

    u64 m = fma2(v, INVPI, MAGIC);
    u64 q = add2(m, NMAGIC);
    u64 r = fma2(q, NPIHI, v);
    r = fma2(q, PMID, r);            // r = v - q*pi, |r| <= pi/2

    u64 s = mul2(r, r);
    u64 p = fma2(s, C8, C6);
    p = fma2(s, p, C4);
    u64 t = fma2(s, NHALF, ONE);
    u64 s2 = mul2(s, s);
    u64 c = fma2(s2, p, t);          // cos(r)

    u64 par = (m << 31) & 0x8000000080000000ULL;  // parity sign of q
    c ^= par;

    u64 u = fma2(c, HALF, HALF);     // into [0,1]
    u64 om = fma2(u, NONE, ONE);
    u = mul2(mul2(u, om), RR);
    om = fma2(u, NONE, ONE);
    u = mul2(u, om);
    if (FOLD_R) u = mul2(u, RR);
    return u;
}

// ---------------- geometry & shared layout (u64 units) ----------------
#define TPB 256
#define PPB 512
#define HS_OFF    0        // float2[64][256] -> 16384 u64
#define W1X0_OFF  16384    // 32 (pairs of W1[:,0])
#define W1X1_OFF  16416    // 32 (pairs of W1[:,1])
#define W4D_OFF   16448    // 64 (dup'd, R-scaled)
#define B1P_OFF   16512    // 32 j-pairs
#define B2P_OFF   16544    // 32
#define B3P_OFF   16576    // 32
#define B4D_OFF   16608    // 1
#define SMEM_U64  16609
#define SMEM_BYTES (SMEM_U64 * 8)   // 132872 B

// One 64->64 layer, output-pair packing, weights from __constant__.
// hsF: float2 per (k,tid): (.x = point A, .y = point B)
template <int LAYER>
__device__ __forceinline__ void layerC(const u64* __restrict__ bp,
                                       float2* __restrict__ hsF, int tid) {
    u64 hout[64];  // [tile][0..15]=A-pairs, [tile][16..31]=B-pairs
#pragma unroll
    for (int t = 0; t < 2; ++t) {
        u64 accA[16], accB[16];
#pragma unroll
        for (int p = 0; p < 16; ++p) { accA[p] = bp[t * 16 + p]; accB[p] = accA[p]; }
#pragma unroll 4
        for (int k = 0; k < 64; ++k) {
            float2 h = hsF[k * TPB + tid];
            u64 dA = pack2(h.x, h.x);
            u64 dB = pack2(h.y, h.y);
#pragma unroll
            for (int p2 = 0; p2 < 8; ++p2) {
                ulonglong2 w = (LAYER == 2) ? CW2[k * 16 + t * 8 + p2]
                                            : CW3[k * 16 + t * 8 + p2];
                accA[2 * p2]     = fma2(dA, w.x, accA[2 * p2]);
                accB[2 * p2]     = fma2(dB, w.x, accB[2 * p2]);
                accA[2 * p2 + 1] = fma2(dA, w.y, accA[2 * p2 + 1]);
                accB[2 * p2 + 1] = fma2(dB, w.y, accB[2 * p2 + 1]);
            }
        }
#pragma unroll
        for (int p = 0; p < 16; ++p) {
            hout[t * 32 + p]      = act2_t<0>(accA[p]);
            hout[t * 32 + 16 + p] = act2_t<0>(accB[p]);
        }
    }
    // writeback: convert (j,j+1)-pairs back to (A,B) scalar float2 per j
#pragma unroll
    for (int jp = 0; jp < 32; ++jp) {
        int t = jp >> 4, p = jp & 15;
        float a0, a1, b0, b1;
        unpack2(hout[t * 32 + p], a0, a1);
        unpack2(hout[t * 32 + 16 + p], b0, b1);
        hsF[(2 * jp) * TPB + tid]     = make_float2(a0, b0);
        hsF[(2 * jp + 1) * TPB + tid] = make_float2(a1, b1);
    }
}

__global__ void __launch_bounds__(TPB, 1)
mlp_kernel(const float* __restrict__ x,
           const float* __restrict__ W1, const float* __restrict__ b1,
           const float* __restrict__ b2, const float* __restrict__ b3,
           const float* __restrict__ W4, const float* __restrict__ b4,
           float* __restrict__ out, int N) {
    extern __shared__ u64 sm[];
    const int tid = threadIdx.x;

    // ---- stage small operands (W1/W4/biases) in SMEM ----
    if (tid < 32) {
        sm[W1X0_OFF + tid] = pack2(W1[(2 * tid) * 2 + 0], W1[(2 * tid + 1) * 2 + 0]);
        sm[W1X1_OFF + tid] = pack2(W1[(2 * tid) * 2 + 1], W1[(2 * tid + 1) * 2 + 1]);
        sm[B1P_OFF + tid] = pack2(b1[2 * tid], b1[2 * tid + 1]);
        sm[B2P_OFF + tid] = pack2(b2[2 * tid], b2[2 * tid + 1]);
        sm[B3P_OFF + tid] = pack2(b3[2 * tid], b3[2 * tid + 1]);
    }
    if (tid < 64) sm[W4D_OFF + tid] = dup2(R_CONST * W4[tid]);
    if (tid == 0) sm[B4D_OFF] = dup2(b4[0]);
    __syncthreads();

    float2* hsF = (float2*)(sm + HS_OFF);
    const u64* hsU = sm + HS_OFF;

    const int i0 = blockIdx.x * PPB + tid;
    const int i1 = i0 + TPB;
    const bool v0 = i0 < N, v1 = i1 < N;

    float2 xa = v0 ? ((const float2*)x)[i0] : make_float2(0.f, 0.f);
    float2 xb = v1 ? ((const float2*)x)[i1] : make_float2(0.f, 0.f);

    // ---- layer 1: 2 -> 64 (output-pair packed, outer R folded into W2) ----
    {
        u64 dA0 = pack2(xa.x, xa.x), dA1 = pack2(xa.y, xa.y);
        u64 dB0 = pack2(xb.x, xb.x), dB1 = pack2(xb.y, xb.y);
        const u64* w0 = sm + W1X0_OFF;
        const u64* w1 = sm + W1X1_OFF;
        const u64* bp = sm + B1P_OFF;
#pragma unroll 8
        for (int jp = 0; jp < 32; ++jp) {
            u64 pA = fma2(dA0, w0[jp], fma2(dA1, w1[jp], bp[jp]));
            u64 pB = fma2(dB0, w0[jp], fma2(dB1, w1[jp], bp[jp]));
            u64 aA = act2_t<0>(pA);
            u64 aB = act2_t<0>(pB);
            float a0, a1, b0, b1;
            unpack2(aA, a0, a1);
            unpack2(aB, b0, b1);
            hsF[(2 * jp) * TPB + tid]     = make_float2(a0, b0);
            hsF[(2 * jp + 1) * TPB + tid] = make_float2(a1, b1);
        }
    }

    // ---- layers 2, 3: 64 -> 64 (weights via constant port) ----
    layerC<2>(sm + B2P_OFF, hsF, tid);
    layerC<3>(sm + B3P_OFF, hsF, tid);

    // ---- layer 4: 64 -> 1 (hs float2 is already points-packed) ----
    {
        const u64* w4d = sm + W4D_OFF;
        u64 a0 = sm[B4D_OFF], a1 = dup2(0.f), a2 = dup2(0.f), a3 = dup2(0.f);
#pragma unroll 8
        for (int k = 0; k < 64; k += 4) {
            a0 = fma2(hsU[(k + 0) * TPB + tid], w4d[k + 0], a0);
            a1 = fma2(hsU[(k + 1) * TPB + tid], w4d[k + 1], a1);
            a2 = fma2(hsU[(k + 2) * TPB + tid], w4d[k + 2], a2);
            a3 = fma2(hsU[(k + 3) * TPB + tid], w4d[k + 3], a3);
        }
        u64 acc = add2(add2(a0, a1), add2(a2, a3));
        u64 o = act2_t<1>(acc);   // final activation keeps its R
        float oa, ob;
        unpack2(o, oa, ob);
        if (v0) out[i0] = oa;
        if (v1) out[i1] = ob;
    }
}

extern "C" void kernel_launch(void* const* d_in, const int* in_sizes, int n_in,
                              void* d_out, int out_size) {
    const float* x  = (const float*)d_in[0];
    const float* W1 = (const float*)d_in[1];
    const float* b1 = (const float*)d_in[2];
    const float* W2 = (const float*)d_in[3];
    const float* b2 = (const float*)d_in[4];
    const float* W3 = (const float*)d_in[5];
    const float* b3 = (const float*)d_in[6];
    const float* W4 = (const float*)d_in[7];
    const float* b4 = (const float*)d_in[8];
    float* out = (float*)d_out;

    int N = in_sizes[0] / 2;
    int grid = (N + PPB - 1) / PPB;

    // 1) pack/transpose/R-fold W2,W3 into device scratch
    prep_kernel<<<8, 256>>>(W2, W3);

    // 2) device-to-device copy into __constant__ banks (capturable memcpy)
    void* gsrc = nullptr;
    cudaGetSymbolAddress(&gsrc, g_wscratch);
    cudaMemcpyToSymbolAsync(CW2, gsrc, 1024 * sizeof(ulonglong2), 0,
                            cudaMemcpyDeviceToDevice, 0);
    cudaMemcpyToSymbolAsync(CW3, (const char*)gsrc + 1024 * sizeof(ulonglong2),
                            1024 * sizeof(ulonglong2), 0,
                            cudaMemcpyDeviceToDevice, 0);

    // 3) main kernel
    cudaFuncSetAttribute(mlp_kernel, cudaFuncAttributeMaxDynamicSharedMemorySize,
                         SMEM_BYTES);
    mlp_kernel<<<grid, TPB, SMEM_BYTES>>>(x, W1, b1, b2, b3, W4, b4, out, N);
}

// round 15
// speedup vs baseline: 1.8723x; 1.0486x over previous
#include <cuda_runtime.h>
#include <cuda_bf16.h>

typedef unsigned long long u64;

// ---------------- packed f32x2 helpers ----------------
__device__ __forceinline__ u64 fma2(u64 a, u64 b, u64 c) {
    u64 d;
    asm("fma.rn.f32x2 %0, %1, %2, %3;" : "=l"(d) : "l"(a), "l"(b), "l"(c));
    return d;
}
__device__ __forceinline__ u64 mul2(u64 a, u64 b) {
    u64 d;
    asm("mul.rn.f32x2 %0, %1, %2;" : "=l"(d) : "l"(a), "l"(b));
    return d;
}
__device__ __forceinline__ u64 add2(u64 a, u64 b) {
    u64 d;
    asm("add.rn.f32x2 %0, %1, %2;" : "=l"(d) : "l"(a), "l"(b));
    return d;
}
__device__ __forceinline__ u64 pack2(float x, float y) {
    u64 r;
    asm("mov.b64 %0, {%1, %2};" : "=l"(r) : "f"(x), "f"(y));
    return r;
}
__device__ __forceinline__ void unpack2(u64 v, float& x, float& y) {
    asm("mov.b64 {%0, %1}, %2;" : "=f"(x), "=f"(y) : "l"(v));
}
__device__ __forceinline__ u64 dup2(float f) {
    unsigned u = __float_as_uint(f);
    return ((u64)u << 32) | (u64)u;
}
__device__ __forceinline__ float sin_mufu(float x) {
    float s;
    asm("sin.approx.f32 %0, %1;" : "=f"(s) : "f"(x));
    return s;
}

#define R_CONST 3.82843f

// ---------------- constant-memory weights (W2, W3) ----------------
// Packed layout per layer: ulonglong2[1024]; element (k*16 + q) holds
// j-pairs (4q..4q+3) for k, R-folded. Filled at launch by prep kernel
// + cudaMemcpyToSymbolAsync (D2D, graph-capturable).
__constant__ ulonglong2 CW2[1024];
__constant__ ulonglong2 CW3[1024];
__device__ ulonglong2 g_wscratch[2048];

__global__ void prep_kernel(const float* __restrict__ W2,
                            const float* __restrict__ W3) {
    int t = blockIdx.x * blockDim.x + threadIdx.x;  // 0..2047
    if (t >= 2048) return;
    const float* W = (t & 1024) ? W3 : W2;
    int e = t & 1023;
    int k = e >> 4, q = e & 15;
    ulonglong2 v;
    v.x = pack2(R_CONST * W[(4 * q + 0) * 64 + k],
                R_CONST * W[(4 * q + 1) * 64 + k]);
    v.y = pack2(R_CONST * W[(4 * q + 2) * 64 + k],
                R_CONST * W[(4 * q + 3) * 64 + k]);
    g_wscratch[t] = v;
}

// ---------------- packed activation (MUFU-sin + sin^2 identity) ----------
// act(x) = logistic^2( cos(x)*0.5 + 0.5 ),  logistic(u) = R*u*(1-u)
// Identity: first logistic iter = R*(1-cos^2(x))/4 = (R/4)*sin^2(x),
// and sin^2(x) = sin^2(r) after pi-reduction (sign/parity irrelevant).
// Reduction stays exact fp32 (magic-number, 2-term pi), so MUFU sees
// |r| <= pi/2 where sin.approx error <= ~2^-20.5.
// FOLD_R==0: the final multiply by R is folded into the NEXT layer's weights.
template <int FOLD_R>
__device__ __forceinline__ u64 act2_t(u64 v) {
    const u64 INVPI  = dup2(0.31830988618379067f);
    const u64 MAGIC  = dup2(12582912.0f);          // 1.5 * 2^23
    const u64 NMAGIC = dup2(-12582912.0f);
    const u64 NPIHI  = dup2(-3.14159274101257324f);
    const u64 PMID   = dup2(8.742277657347586e-8f);
    const u64 ONE    = dup2(1.0f);
    const u64 NONE   = dup2(-1.0f);
    const u64 R4     = dup2(R_CONST * 0.25f);
    const u64 RR     = dup2(R_CONST);

    u64 m = fma2(v, INVPI, MAGIC);
    u64 q = add2(m, NMAGIC);
    u64 r = fma2(q, NPIHI, v);
    r = fma2(q, PMID, r);            // r = v - q*pi, |r| <= pi/2

    float r0, r1;
    unpack2(r, r0, r1);
    u64 sp = pack2(sin_mufu(r0), sin_mufu(r1));

    u64 s2 = mul2(sp, sp);           // sin^2(r) = sin^2(x)
    u64 u = mul2(s2, R4);            // first logistic iteration
    u64 om = fma2(u, NONE, ONE);     // second iteration
    u = mul2(u, om);
    if (FOLD_R) u = mul2(u, RR);
    return u;
}

// ---------------- geometry & shared layout (u64 units) ----------------
#define TPB 256
#define PPB 512
#define HS_OFF    0        // float2[64][256] -> 16384 u64
#define W1X0_OFF  16384    // 32 (pairs of W1[:,0])
#define W1X1_OFF  16416    // 32 (pairs of W1[:,1])
#define W4D_OFF   16448    // 64 (dup'd, R-scaled)
#define B1P_OFF   16512    // 32 j-pairs
#define B2P_OFF   16544    // 32
#define B3P_OFF   16576    // 32
#define B4D_OFF   16608    // 1
#define SMEM_U64  16609
#define SMEM_BYTES (SMEM_U64 * 8)   // 132872 B

// One 64->64 layer, output-pair packing, weights from __constant__.
// hsF: float2 per (k,tid): (.x = point A, .y = point B)
template <int LAYER>
__device__ __forceinline__ void layerC(const u64* __restrict__ bp,
                                       float2* __restrict__ hsF, int tid) {
    u64 hout[64];  // [tile][0..15]=A-pairs, [tile][16..31]=B-pairs
#pragma unroll
    for (int t = 0; t < 2; ++t) {
        u64 accA[16], accB[16];
#pragma unroll
        for (int p = 0; p < 16; ++p) { accA[p] = bp[t * 16 + p]; accB[p] = accA[p]; }
#pragma unroll 4
        for (int k = 0; k < 64; ++k) {
            float2 h = hsF[k * TPB + tid];
            u64 dA = pack2(h.x, h.x);
            u64 dB = pack2(h.y, h.y);
#pragma unroll
            for (int p2 = 0; p2 < 8; ++p2) {
                ulonglong2 w = (LAYER == 2) ? CW2[k * 16 + t * 8 + p2]
                                            : CW3[k * 16 + t * 8 + p2];
                accA[2 * p2]     = fma2(dA, w.x, accA[2 * p2]);
                accB[2 * p2]     = fma2(dB, w.x, accB[2 * p2]);
                accA[2 * p2 + 1] = fma2(dA, w.y, accA[2 * p2 + 1]);
                accB[2 * p2 + 1] = fma2(dB, w.y, accB[2 * p2 + 1]);
            }
        }
#pragma unroll
        for (int p = 0; p < 16; ++p) {
            hout[t * 32 + p]      = act2_t<0>(accA[p]);
            hout[t * 32 + 16 + p] = act2_t<0>(accB[p]);
        }
    }
    // writeback: convert (j,j+1)-pairs back to (A,B) scalar float2 per j
#pragma unroll
    for (int jp = 0; jp < 32; ++jp) {
        int t = jp >> 4, p = jp & 15;
        float a0, a1, b0, b1;
        unpack2(hout[t * 32 + p], a0, a1);
        unpack2(hout[t * 32 + 16 + p], b0, b1);
        hsF[(2 * jp) * TPB + tid]     = make_float2(a0, b0);
        hsF[(2 * jp + 1) * TPB + tid] = make_float2(a1, b1);
    }
}

__global__ void __launch_bounds__(TPB, 1)
mlp_kernel(const float* __restrict__ x,
           const float* __restrict__ W1, const float* __restrict__ b1,
           const float* __restrict__ b2, const float* __restrict__ b3,
           const float* __restrict__ W4, const float* __restrict__ b4,
           float* __restrict__ out, int N) {
    extern __shared__ u64 sm[];
    const int tid = threadIdx.x;

    // ---- stage small operands (W1/W4/biases) in SMEM ----
    if (tid < 32) {
        sm[W1X0_OFF + tid] = pack2(W1[(2 * tid) * 2 + 0], W1[(2 * tid + 1) * 2 + 0]);
        sm[W1X1_OFF + tid] = pack2(W1[(2 * tid) * 2 + 1], W1[(2 * tid + 1) * 2 + 1]);
        sm[B1P_OFF + tid] = pack2(b1[2 * tid], b1[2 * tid + 1]);
        sm[B2P_OFF + tid] = pack2(b2[2 * tid], b2[2 * tid + 1]);
        sm[B3P_OFF + tid] = pack2(b3[2 * tid], b3[2 * tid + 1]);
    }
    if (tid < 64) sm[W4D_OFF + tid] = dup2(R_CONST * W4[tid]);
    if (tid == 0) sm[B4D_OFF] = dup2(b4[0]);
    __syncthreads();

    float2* hsF = (float2*)(sm + HS_OFF);
    const u64* hsU = sm + HS_OFF;

    const int i0 = blockIdx.x * PPB + tid;
    const int i1 = i0 + TPB;
    const bool v0 = i0 < N, v1 = i1 < N;

    float2 xa = v0 ? ((const float2*)x)[i0] : make_float2(0.f, 0.f);
    float2 xb = v1 ? ((const float2*)x)[i1] : make_float2(0.f, 0.f);

    // ---- layer 1: 2 -> 64 (output-pair packed, outer R folded into W2) ----
    {
        u64 dA0 = pack2(xa.x, xa.x), dA1 = pack2(xa.y, xa.y);
        u64 dB0 = pack2(xb.x, xb.x), dB1 = pack2(xb.y, xb.y);
        const u64* w0 = sm + W1X0_OFF;
        const u64* w1 = sm + W1X1_OFF;
        const u64* bp = sm + B1P_OFF;
#pragma unroll 8
        for (int jp = 0; jp < 32; ++jp) {
            u64 pA = fma2(dA0, w0[jp], fma2(dA1, w1[jp], bp[jp]));
            u64 pB = fma2(dB0, w0[jp], fma2(dB1, w1[jp], bp[jp]));
            u64 aA = act2_t<0>(pA);
            u64 aB = act2_t<0>(pB);
            float a0, a1, b0, b1;
            unpack2(aA, a0, a1);
            unpack2(aB, b0, b1);
            hsF[(2 * jp) * TPB + tid]     = make_float2(a0, b0);
            hsF[(2 * jp + 1) * TPB + tid] = make_float2(a1, b1);
        }
    }

    // ---- layers 2, 3: 64 -> 64 (weights via constant port) ----
    layerC<2>(sm + B2P_OFF, hsF, tid);
    layerC<3>(sm + B3P_OFF, hsF, tid);

    // ---- layer 4: 64 -> 1 (hs float2 is already points-packed) ----
    {
        const u64* w4d = sm + W4D_OFF;
        u64 a0 = sm[B4D_OFF], a1 = dup2(0.f), a2 = dup2(0.f), a3 = dup2(0.f);
#pragma unroll 8
        for (int k = 0; k < 64; k += 4) {
            a0 = fma2(hsU[(k + 0) * TPB + tid], w4d[k + 0], a0);
            a1 = fma2(hsU[(k + 1) * TPB + tid], w4d[k + 1], a1);
            a2 = fma2(hsU[(k + 2) * TPB + tid], w4d[k + 2], a2);
            a3 = fma2(hsU[(k + 3) * TPB + tid], w4d[k + 3], a3);
        }
        u64 acc = add2(add2(a0, a1), add2(a2, a3));
        u64 o = act2_t<1>(acc);   // final activation keeps its R
        float oa, ob;
        unpack2(o, oa, ob);
        if (v0) out[i0] = oa;
        if (v1) out[i1] = ob;
    }
}

extern "C" void kernel_launch(void* const* d_in, const int* in_sizes, int n_in,
                              void* d_out, int out_size) {
    const float* x  = (const float*)d_in[0];
    const float* W1 = (const float*)d_in[1];
    const float* b1 = (const float*)d_in[2];
    const float* W2 = (const float*)d_in[3];
    const float* b2 = (const float*)d_in[4];
    const float* W3 = (const float*)d_in[5];
    const float* b3 = (const float*)d_in[6];
    const float* W4 = (const float*)d_in[7];
    const float* b4 = (const float*)d_in[8];
    float* out = (float*)d_out;

    int N = in_sizes[0] / 2;
    int grid = (N + PPB - 1) / PPB;

    // 1) pack/transpose/R-fold W2,W3 into device scratch
    prep_kernel<<<8, 256>>>(W2, W3);

    // 2) device-to-device copy into __constant__ banks (capturable memcpy)
    void* gsrc = nullptr;
    cudaGetSymbolAddress(&gsrc, g_wscratch);
    cudaMemcpyToSymbolAsync(CW2, gsrc, 1024 * sizeof(ulonglong2), 0,
                            cudaMemcpyDeviceToDevice, 0);
    cudaMemcpyToSymbolAsync(CW3, (const char*)gsrc + 1024 * sizeof(ulonglong2),
                            1024 * sizeof(ulonglong2), 0,
                            cudaMemcpyDeviceToDevice, 0);

    // 3) main kernel
    cudaFuncSetAttribute(mlp_kernel, cudaFuncAttributeMaxDynamicSharedMemorySize,
                         SMEM_BYTES);
    mlp_kernel<<<grid, TPB, SMEM_BYTES>>>(x, W1, b1, b2, b3, W4, b4, out, N);
}